// round 15
// baseline (speedup 1.0000x reference)
#include <cuda_runtime.h>
#include <math.h>

#define NN   100000
#define EE   3200000
#define INC  256
#define HIDC 32
#define OUTC 40

// ---------------- scratch (static device globals; no allocation) ----------------
__device__ float g_dinv[NN];          // D^-1/2 (with self-loop)
__device__ int   g_degi[NN];          // incoming-edge counts
__device__ int   g_off [NN];          // CSR row offsets (exclusive)
__device__ int   g_cur [NN];          // fill cursors
__device__ int   g_part [128];        // scan partials
__device__ int   g_part2[128];        // scanned partials
__device__ int   g_csrc[EE];          // CSR: source node per slot
__device__ float g_cw  [EE];          // CSR: edge weight dinv[s]*dinv[d]
__device__ float g_h1  [NN * HIDC];   // x @ W1
__device__ float g_helu[NN * HIDC];   // elu(agg1 + b1)
__device__ float g_h2  [NN * OUTC];   // relu(bn(helu)) @ W2
__device__ float g_bn[128];           // [0:32) sum, [32:64) sumsq, [64:96) scale, [96:128) shift
__device__ int   g_is32;              // 1 if edge_index buffer holds int32, 0 if int64

// ---------------- edge-index access (dtype-agnostic) ----------------
__device__ __forceinline__ int eidx(const void* ei, long long pos, int is32) {
    if (is32) return ((const int*)ei)[pos];
    return (int)((const long long*)ei)[pos];
}

// probe dtype: int64 indices are < NN; int32 data viewed as int64 is huge w.p. ~1
__global__ void k_probe(const void* ei) {
    if (threadIdx.x == 0) {
        const unsigned long long* p = (const unsigned long long*)ei;
        int is32 = 0;
        for (int i = 0; i < 64; i++)
            if (p[i] >= (unsigned long long)NN) is32 = 1;
        g_is32 = is32;
    }
}

// ---------------- build kernels ----------------
__global__ void k_init() {
    int i = blockIdx.x * 256 + threadIdx.x;
    if (i < NN) g_degi[i] = 0;
    if (blockIdx.x == 0 && threadIdx.x < 64) g_bn[threadIdx.x] = 0.0f;
}

__global__ void k_deg(const void* __restrict__ ei) {
    int e = blockIdx.x * 256 + threadIdx.x;
    if (e >= EE) return;
    int is32 = g_is32;
    int d = eidx(ei, (long long)EE + e, is32);
    if ((unsigned)d < NN) atomicAdd(&g_degi[d], 1);
}

__global__ void k_dinv() {
    int i = blockIdx.x * 256 + threadIdx.x;
    if (i < NN) g_dinv[i] = rsqrtf((float)g_degi[i] + 1.0f);   // +1 self-loop
}

// block-local exclusive scan of degi (1024/block), partial per block
__global__ void k_scan1() {
    __shared__ int s[1024];
    int t = threadIdx.x;
    int i = blockIdx.x * 1024 + t;
    int v = (i < NN) ? g_degi[i] : 0;
    s[t] = v;
    __syncthreads();
    for (int o = 1; o < 1024; o <<= 1) {
        int tv = (t >= o) ? s[t - o] : 0;
        __syncthreads();
        s[t] += tv;
        __syncthreads();
    }
    if (i < NN) g_off[i] = s[t] - v;
    if (t == 1023) g_part[blockIdx.x] = s[1023];
}

__global__ void k_scan2(int nblk) {
    __shared__ int s[128];
    int t = threadIdx.x;
    int v = (t < nblk) ? g_part[t] : 0;
    s[t] = v;
    __syncthreads();
    for (int o = 1; o < 128; o <<= 1) {
        int tv = (t >= o) ? s[t - o] : 0;
        __syncthreads();
        s[t] += tv;
        __syncthreads();
    }
    if (t < nblk) g_part2[t] = s[t] - v;
}

__global__ void k_scan3() {
    int i = blockIdx.x * 256 + threadIdx.x;
    if (i < NN) {
        int o = g_off[i] + g_part2[i >> 10];
        g_off[i] = o;
        g_cur[i] = o;
    }
}

// fill CSR slots (intra-node order nondeterministic; float sums stay within tol)
__global__ void k_fill(const void* __restrict__ ei) {
    int e = blockIdx.x * 256 + threadIdx.x;
    if (e >= EE) return;
    int is32 = g_is32;
    int s = eidx(ei, e, is32);
    int d = eidx(ei, (long long)EE + e, is32);
    if ((unsigned)s >= NN || (unsigned)d >= NN) return;
    int pos = atomicAdd(&g_cur[d], 1);
    if (pos < EE) {
        g_csrc[pos] = s;
        g_cw[pos]   = g_dinv[s] * g_dinv[d];
    }
}

// ---------------- GEMM1: h1 = x @ W1  [N,256]x[256,32] ----------------
// 32 rows/block, 2 k-chunks of 128; warp w computes rows 4w..4w+3, lane = column.
__global__ void k_gemm1(const float* __restrict__ x, const float* __restrict__ W1) {
    __shared__ float Ws[128 * 32];    // 16 KB (k-chunk of W1)
    __shared__ float Xs[32][132];     // 16.5 KB (32 rows x 128 k, +4 pad)
    const int tid  = threadIdx.x;
    const int row0 = blockIdx.x * 32;
    const int lane = tid & 31, w = tid >> 5;

    float acc0 = 0.f, acc1 = 0.f, acc2 = 0.f, acc3 = 0.f;

    for (int kc = 0; kc < 2; kc++) {
        for (int i = tid; i < 128 * 32; i += 256)
            Ws[i] = W1[kc * 128 * 32 + i];
        for (int i = tid; i < 32 * 128; i += 256) {
            int r = i >> 7, k = i & 127;
            int row = row0 + r;
            Xs[r][k] = (row < NN) ? x[(size_t)row * INC + kc * 128 + k] : 0.0f;
        }
        __syncthreads();

        const int r0 = w * 4;
#pragma unroll 8
        for (int k = 0; k < 128; k++) {
            float wv = Ws[k * 32 + lane];
            acc0 += Xs[r0 + 0][k] * wv;
            acc1 += Xs[r0 + 1][k] * wv;
            acc2 += Xs[r0 + 2][k] * wv;
            acc3 += Xs[r0 + 3][k] * wv;
        }
        __syncthreads();
    }

    int r = row0 + w * 4;
    if (r + 0 < NN) g_h1[(r + 0) * HIDC + lane] = acc0;
    if (r + 1 < NN) g_h1[(r + 1) * HIDC + lane] = acc1;
    if (r + 2 < NN) g_h1[(r + 2) * HIDC + lane] = acc2;
    if (r + 3 < NN) g_h1[(r + 3) * HIDC + lane] = acc3;
}

// ---------------- gather layer 1 (fused +b1, ELU, BN stats) ----------------
// one warp per node; lane = channel; 32-edge chunks broadcast via shfl
__global__ void k_gather1(const float* __restrict__ b1) {
    __shared__ float sbn[64];
    int tid = threadIdx.x;
    if (tid < 64) sbn[tid] = 0.0f;
    __syncthreads();

    int lane = tid & 31;
    int r = blockIdx.x * 8 + (tid >> 5);          // 12500*8 = 100000 exact
    int beg = g_off[r];
    int end = (r == NN - 1) ? g_cur[r] : g_off[r + 1];
    float dv = g_dinv[r];
    float acc = g_h1[r * HIDC + lane] * dv * dv;  // self-loop term

    int base = beg;
    while (end - base >= 32) {
        int   sreg = g_csrc[base + lane];
        float wreg = g_cw[base + lane];
#pragma unroll
        for (int i = 0; i < 32; i++) {
            int   si = __shfl_sync(0xffffffffu, sreg, i);
            float wi = __shfl_sync(0xffffffffu, wreg, i);
            acc += g_h1[si * HIDC + lane] * wi;
        }
        base += 32;
    }
    if (base < end) {
        int n = end - base;
        int   sreg = 0; float wreg = 0.0f;
        if (lane < n) { sreg = g_csrc[base + lane]; wreg = g_cw[base + lane]; }
        for (int i = 0; i < n; i++) {
            int   si = __shfl_sync(0xffffffffu, sreg, i);
            float wi = __shfl_sync(0xffffffffu, wreg, i);
            acc += g_h1[si * HIDC + lane] * wi;
        }
    }

    float v = acc + b1[lane];
    float h = (v > 0.0f) ? v : expm1f(v);         // ELU
    g_helu[r * HIDC + lane] = h;

    atomicAdd(&sbn[lane],      h);
    atomicAdd(&sbn[32 + lane], h * h);
    __syncthreads();
    if (tid < 64) atomicAdd(&g_bn[tid], sbn[tid]);
}

__global__ void k_bnfinal() {
    int j = threadIdx.x;
    float mean = g_bn[j] * (1.0f / NN);
    float var  = g_bn[32 + j] * (1.0f / NN) - mean * mean;
    float sc   = rsqrtf(var + 1e-5f);
    g_bn[64 + j] = sc;
    g_bn[96 + j] = -mean * sc;
}

// ---------------- GEMM2: h2 = relu(bn(helu)) @ W2  [N,32]x[32,40] ----------------
__global__ void k_gemm2(const float* __restrict__ W2) {
    __shared__ float Hs[64 * 33];
    __shared__ float W2s[HIDC * OUTC];
    int tid  = threadIdx.x;
    int row0 = blockIdx.x * 64;
    for (int i = tid; i < HIDC * OUTC; i += 256) W2s[i] = W2[i];
    for (int i = tid; i < 64 * 32; i += 256) {
        int r = i >> 5, j = i & 31;
        int row = row0 + r;
        float v = (row < NN) ? g_helu[row * HIDC + j] : 0.0f;
        float y = v * g_bn[64 + j] + g_bn[96 + j];
        Hs[r * 33 + j] = (y > 0.0f) ? y : 0.0f;
    }
    __syncthreads();
#pragma unroll
    for (int ii = 0; ii < 10; ii++) {
        int e = ii * 256 + tid;                   // 2560 = 64 rows * 40 cols
        int r = e / 40, c = e - r * 40;
        int row = row0 + r;
        float acc = 0.0f;
#pragma unroll
        for (int k = 0; k < HIDC; k++) acc += Hs[r * 33 + k] * W2s[k * OUTC + c];
        if (row < NN) g_h2[row * OUTC + c] = acc;
    }
}

// ---------------- gather layer 2 (fused +b2, log_softmax) ----------------
__global__ void k_gather2(const float* __restrict__ b2, float* __restrict__ out) {
    int tid = threadIdx.x;
    int lane = tid & 31;
    int r = blockIdx.x * 8 + (tid >> 5);
    int beg = g_off[r];
    int end = (r == NN - 1) ? g_cur[r] : g_off[r + 1];
    float dv = g_dinv[r];
    float a0 = g_h2[r * OUTC + lane] * dv * dv;
    float a1 = (lane < 8) ? g_h2[r * OUTC + 32 + lane] * dv * dv : 0.0f;

    int base = beg;
    while (end - base >= 32) {
        int   sreg = g_csrc[base + lane];
        float wreg = g_cw[base + lane];
#pragma unroll
        for (int i = 0; i < 32; i++) {
            int   si = __shfl_sync(0xffffffffu, sreg, i);
            float wi = __shfl_sync(0xffffffffu, wreg, i);
            a0 += g_h2[si * OUTC + lane] * wi;
            if (lane < 8) a1 += g_h2[si * OUTC + 32 + lane] * wi;
        }
        base += 32;
    }
    if (base < end) {
        int n = end - base;
        int   sreg = 0; float wreg = 0.0f;
        if (lane < n) { sreg = g_csrc[base + lane]; wreg = g_cw[base + lane]; }
        for (int i = 0; i < n; i++) {
            int   si = __shfl_sync(0xffffffffu, sreg, i);
            float wi = __shfl_sync(0xffffffffu, wreg, i);
            a0 += g_h2[si * OUTC + lane] * wi;
            if (lane < 8) a1 += g_h2[si * OUTC + 32 + lane] * wi;
        }
    }

    a0 += b2[lane];
    a1 = (lane < 8) ? (a1 + b2[32 + lane]) : -1e30f;

    float m = fmaxf(a0, a1);
#pragma unroll
    for (int o = 16; o > 0; o >>= 1) m = fmaxf(m, __shfl_xor_sync(0xffffffffu, m, o));
    float s = expf(a0 - m) + ((lane < 8) ? expf(a1 - m) : 0.0f);
#pragma unroll
    for (int o = 16; o > 0; o >>= 1) s += __shfl_xor_sync(0xffffffffu, s, o);
    float lse = logf(s) + m;
    out[r * OUTC + lane] = a0 - lse;
    if (lane < 8) out[r * OUTC + 32 + lane] = a1 - lse;
}

// ---------------- launch ----------------
extern "C" void kernel_launch(void* const* d_in, const int* in_sizes, int n_in,
                              void* d_out, int out_size) {
    // Bind inputs by element count (sizes are pairwise distinct) — robust to
    // metadata ordering. Fall back to positional if a size is missing.
    const float* x  = (const float*)d_in[0];
    const void*  ei = d_in[1];
    const float* W1 = (const float*)d_in[2];
    const float* b1 = (const float*)d_in[3];
    const float* W2 = (const float*)d_in[4];
    const float* b2 = (const float*)d_in[5];
    for (int i = 0; i < n_in; i++) {
        switch (in_sizes[i]) {
            case NN * INC:     x  = (const float*)d_in[i]; break;  // 25,600,000
            case 2 * EE:       ei = d_in[i];               break;  //  6,400,000
            case INC * HIDC:   W1 = (const float*)d_in[i]; break;  //      8,192
            case HIDC:         b1 = (const float*)d_in[i]; break;  //         32
            case HIDC * OUTC:  W2 = (const float*)d_in[i]; break;  //      1,280
            case OUTC:         b2 = (const float*)d_in[i]; break;  //         40
            default: break;
        }
    }
    float* out = (float*)d_out;

    const int NSCAN = (NN + 1023) / 1024;   // 98

    k_probe  <<<1, 32>>>(ei);
    k_init   <<<(NN + 255) / 256, 256>>>();
    k_deg    <<<(EE + 255) / 256, 256>>>(ei);
    k_dinv   <<<(NN + 255) / 256, 256>>>();
    k_scan1  <<<NSCAN, 1024>>>();
    k_scan2  <<<1, 128>>>(NSCAN);
    k_scan3  <<<(NN + 255) / 256, 256>>>();
    k_fill   <<<(EE + 255) / 256, 256>>>(ei);
    k_gemm1  <<<(NN + 31) / 32, 256>>>(x, W1);
    k_gather1<<<NN / 8, 256>>>(b1);
    k_bnfinal<<<1, 32>>>();
    k_gemm2  <<<(NN + 63) / 64, 256>>>(W2);
    k_gather2<<<NN / 8, 256>>>(b2, out);
}

// round 16
// speedup vs baseline: 1.0855x; 1.0855x over previous
#include <cuda_runtime.h>
#include <math.h>

#define NN   100000
#define EE   3200000
#define INC  256
#define HIDC 32
#define OUTC 40

// ---------------- scratch (static device globals; no allocation) ----------------
__device__ float g_dinv[NN];          // D^-1/2 (with self-loop)
__device__ int   g_degi[NN];          // incoming-edge counts
__device__ int   g_off [NN];          // CSR row offsets (exclusive)
__device__ int   g_cur [NN];          // fill cursors (== row end after fill)
__device__ int   g_part [128];        // scan partials
__device__ int   g_part2[128];        // scanned partials
__device__ int2  g_csr[EE];           // CSR: {src, weight-bits} packed per slot
__device__ float g_h1  [NN * HIDC];   // x @ W1
__device__ float g_helu[NN * HIDC];   // elu(agg1 + b1)
__device__ float g_y   [NN * HIDC];   // relu(bn(helu))
__device__ float g_bn[128];           // [0:32) sum, [32:64) sumsq, [64:96) scale, [96:128) shift
__device__ int   g_is32;              // 1 if edge_index holds int32, 0 if int64

// ---------------- edge-index access (dtype-agnostic) ----------------
__device__ __forceinline__ int eidx(const void* ei, long long pos, int is32) {
    if (is32) return ((const int*)ei)[pos];
    return (int)((const long long*)ei)[pos];
}

__global__ void k_probe(const void* ei) {
    if (threadIdx.x == 0) {
        const unsigned long long* p = (const unsigned long long*)ei;
        int is32 = 0;
        for (int i = 0; i < 64; i++)
            if (p[i] >= (unsigned long long)NN) is32 = 1;
        g_is32 = is32;
    }
}

// ---------------- build kernels ----------------
__global__ void k_init() {
    int i = blockIdx.x * 256 + threadIdx.x;
    if (i < NN) g_degi[i] = 0;
    if (blockIdx.x == 0 && threadIdx.x < 64) g_bn[threadIdx.x] = 0.0f;
}

__global__ void k_deg(const void* __restrict__ ei) {
    int e = blockIdx.x * 256 + threadIdx.x;
    if (e >= EE) return;
    int d = eidx(ei, (long long)EE + e, g_is32);
    if ((unsigned)d < NN) atomicAdd(&g_degi[d], 1);
}

__global__ void k_dinv() {
    int i = blockIdx.x * 256 + threadIdx.x;
    if (i < NN) g_dinv[i] = rsqrtf((float)g_degi[i] + 1.0f);   // +1 self-loop
}

__global__ void k_scan1() {
    __shared__ int s[1024];
    int t = threadIdx.x;
    int i = blockIdx.x * 1024 + t;
    int v = (i < NN) ? g_degi[i] : 0;
    s[t] = v;
    __syncthreads();
    for (int o = 1; o < 1024; o <<= 1) {
        int tv = (t >= o) ? s[t - o] : 0;
        __syncthreads();
        s[t] += tv;
        __syncthreads();
    }
    if (i < NN) g_off[i] = s[t] - v;
    if (t == 1023) g_part[blockIdx.x] = s[1023];
}

__global__ void k_scan2(int nblk) {
    __shared__ int s[128];
    int t = threadIdx.x;
    int v = (t < nblk) ? g_part[t] : 0;
    s[t] = v;
    __syncthreads();
    for (int o = 1; o < 128; o <<= 1) {
        int tv = (t >= o) ? s[t - o] : 0;
        __syncthreads();
        s[t] += tv;
        __syncthreads();
    }
    if (t < nblk) g_part2[t] = s[t] - v;
}

__global__ void k_scan3() {
    int i = blockIdx.x * 256 + threadIdx.x;
    if (i < NN) {
        int o = g_off[i] + g_part2[i >> 10];
        g_off[i] = o;
        g_cur[i] = o;
    }
}

// fill packed CSR slots (intra-node order nondeterministic; sums stay within tol)
__global__ void k_fill(const void* __restrict__ ei) {
    int e = blockIdx.x * 256 + threadIdx.x;
    if (e >= EE) return;
    int is32 = g_is32;
    int s = eidx(ei, e, is32);
    int d = eidx(ei, (long long)EE + e, is32);
    if ((unsigned)s >= NN || (unsigned)d >= NN) return;
    int pos = atomicAdd(&g_cur[d], 1);
    if (pos < EE)
        g_csr[pos] = make_int2(s, __float_as_int(g_dinv[s] * g_dinv[d]));
}

// ---------------- GEMM1: h1 = x @ W1  [N,256]x[256,32] ----------------
__global__ void k_gemm1(const float* __restrict__ x, const float* __restrict__ W1) {
    __shared__ float Ws[128 * 32];
    __shared__ float Xs[32][132];
    const int tid  = threadIdx.x;
    const int row0 = blockIdx.x * 32;
    const int lane = tid & 31, w = tid >> 5;

    float acc0 = 0.f, acc1 = 0.f, acc2 = 0.f, acc3 = 0.f;

    for (int kc = 0; kc < 2; kc++) {
        for (int i = tid; i < 128 * 32; i += 256)
            Ws[i] = W1[kc * 128 * 32 + i];
        for (int i = tid; i < 32 * 128; i += 256) {
            int r = i >> 7, k = i & 127;
            int row = row0 + r;
            Xs[r][k] = (row < NN) ? x[(size_t)row * INC + kc * 128 + k] : 0.0f;
        }
        __syncthreads();

        const int r0 = w * 4;
#pragma unroll 8
        for (int k = 0; k < 128; k++) {
            float wv = Ws[k * 32 + lane];
            acc0 += Xs[r0 + 0][k] * wv;
            acc1 += Xs[r0 + 1][k] * wv;
            acc2 += Xs[r0 + 2][k] * wv;
            acc3 += Xs[r0 + 3][k] * wv;
        }
        __syncthreads();
    }

    int r = row0 + w * 4;
    if (r + 0 < NN) g_h1[(r + 0) * HIDC + lane] = acc0;
    if (r + 1 < NN) g_h1[(r + 1) * HIDC + lane] = acc1;
    if (r + 2 < NN) g_h1[(r + 2) * HIDC + lane] = acc2;
    if (r + 3 < NN) g_h1[(r + 3) * HIDC + lane] = acc3;
}

// ---------------- gather layer 1 (fused +b1, ELU, BN stats) ----------------
__global__ void k_gather1(const float* __restrict__ b1) {
    __shared__ float sbn[64];
    int tid = threadIdx.x;
    if (tid < 64) sbn[tid] = 0.0f;
    __syncthreads();

    int lane = tid & 31;
    int r = blockIdx.x * 8 + (tid >> 5);          // 12500*8 = 100000 exact
    int base = g_off[r];
    int end  = g_cur[r];                          // row end after fill
    float dv = g_dinv[r];
    float acc = g_h1[r * HIDC + lane] * dv * dv;  // self-loop term

    while (end - base >= 32) {
        int2 v2 = g_csr[base + lane];
#pragma unroll
        for (int i = 0; i < 32; i++) {
            int   si = __shfl_sync(0xffffffffu, v2.x, i);
            float wi = __int_as_float(__shfl_sync(0xffffffffu, v2.y, i));
            acc += g_h1[si * HIDC + lane] * wi;
        }
        base += 32;
    }
    if (base < end) {
        int n = end - base;
        int2 v2 = make_int2(0, 0);
        if (lane < n) v2 = g_csr[base + lane];
        for (int i = 0; i < n; i++) {
            int   si = __shfl_sync(0xffffffffu, v2.x, i);
            float wi = __int_as_float(__shfl_sync(0xffffffffu, v2.y, i));
            acc += g_h1[si * HIDC + lane] * wi;
        }
    }

    float v = acc + b1[lane];
    float h = (v > 0.0f) ? v : expm1f(v);         // ELU
    g_helu[r * HIDC + lane] = h;

    atomicAdd(&sbn[lane],      h);
    atomicAdd(&sbn[32 + lane], h * h);
    __syncthreads();
    if (tid < 64) atomicAdd(&g_bn[tid], sbn[tid]);
}

__global__ void k_bnfinal() {
    int j = threadIdx.x;
    float mean = g_bn[j] * (1.0f / NN);
    float var  = g_bn[32 + j] * (1.0f / NN) - mean * mean;
    float sc   = rsqrtf(var + 1e-5f);
    g_bn[64 + j] = sc;
    g_bn[96 + j] = -mean * sc;
}

// ---------------- y = relu(bn(helu)) (elementwise) ----------------
__global__ void k_bnrelu() {
    int i = blockIdx.x * 256 + threadIdx.x;      // 12500 blocks cover N*32
    if (i < NN * HIDC) {
        int j = i & 31;
        float v = g_helu[i] * g_bn[64 + j] + g_bn[96 + j];
        g_y[i] = (v > 0.0f) ? v : 0.0f;
    }
}

// ---------------- gather layer 2 on y (32ch), fused W2 GEMM + b2 + log_softmax ----
__global__ void k_gather2(const float* __restrict__ W2, const float* __restrict__ b2,
                          float* __restrict__ out) {
    __shared__ float W2s[HIDC * OUTC];   // [k][c] row-major, 1280 floats
    __shared__ float b2s[OUTC];
    int tid = threadIdx.x;
    for (int i = tid; i < HIDC * OUTC; i += 256) W2s[i] = W2[i];
    if (tid < OUTC) b2s[tid] = b2[tid];
    __syncthreads();

    int lane = tid & 31;
    int r = blockIdx.x * 8 + (tid >> 5);
    int base = g_off[r];
    int end  = g_cur[r];
    float dv = g_dinv[r];
    float acc = g_y[r * HIDC + lane] * dv * dv;   // self-loop

    while (end - base >= 32) {
        int2 v2 = g_csr[base + lane];
#pragma unroll
        for (int i = 0; i < 32; i++) {
            int   si = __shfl_sync(0xffffffffu, v2.x, i);
            float wi = __int_as_float(__shfl_sync(0xffffffffu, v2.y, i));
            acc += g_y[si * HIDC + lane] * wi;
        }
        base += 32;
    }
    if (base < end) {
        int n = end - base;
        int2 v2 = make_int2(0, 0);
        if (lane < n) v2 = g_csr[base + lane];
        for (int i = 0; i < n; i++) {
            int   si = __shfl_sync(0xffffffffu, v2.x, i);
            float wi = __int_as_float(__shfl_sync(0xffffffffu, v2.y, i));
            acc += g_y[si * HIDC + lane] * wi;
        }
    }

    // GEMM: out[c] = sum_k aggy[k] * W2[k][c] + b2[c]  (aggy[k] lives in lane k's acc)
    float o0 = b2s[lane];
    float o1 = (lane < 8) ? b2s[32 + lane] : -1e30f;
#pragma unroll
    for (int k = 0; k < HIDC; k++) {
        float yk = __shfl_sync(0xffffffffu, acc, k);
        o0 += yk * W2s[k * OUTC + lane];
        if (lane < 8) o1 += yk * W2s[k * OUTC + 32 + lane];
    }

    // log_softmax over 40 values (o0 on all lanes, o1 on lanes 0..7)
    float m = fmaxf(o0, o1);
#pragma unroll
    for (int o = 16; o > 0; o >>= 1) m = fmaxf(m, __shfl_xor_sync(0xffffffffu, m, o));
    float s = expf(o0 - m) + ((lane < 8) ? expf(o1 - m) : 0.0f);
#pragma unroll
    for (int o = 16; o > 0; o >>= 1) s += __shfl_xor_sync(0xffffffffu, s, o);
    float lse = logf(s) + m;
    out[r * OUTC + lane] = o0 - lse;
    if (lane < 8) out[r * OUTC + 32 + lane] = o1 - lse;
}

// ---------------- launch ----------------
extern "C" void kernel_launch(void* const* d_in, const int* in_sizes, int n_in,
                              void* d_out, int out_size) {
    const float* x  = (const float*)d_in[0];
    const void*  ei = d_in[1];
    const float* W1 = (const float*)d_in[2];
    const float* b1 = (const float*)d_in[3];
    const float* W2 = (const float*)d_in[4];
    const float* b2 = (const float*)d_in[5];
    for (int i = 0; i < n_in; i++) {
        switch (in_sizes[i]) {
            case NN * INC:     x  = (const float*)d_in[i]; break;
            case 2 * EE:       ei = d_in[i];               break;
            case INC * HIDC:   W1 = (const float*)d_in[i]; break;
            case HIDC:         b1 = (const float*)d_in[i]; break;
            case HIDC * OUTC:  W2 = (const float*)d_in[i]; break;
            case OUTC:         b2 = (const float*)d_in[i]; break;
            default: break;
        }
    }
    float* out = (float*)d_out;

    const int NSCAN = (NN + 1023) / 1024;   // 98

    k_probe  <<<1, 32>>>(ei);
    k_init   <<<(NN + 255) / 256, 256>>>();
    k_deg    <<<(EE + 255) / 256, 256>>>(ei);
    k_dinv   <<<(NN + 255) / 256, 256>>>();
    k_scan1  <<<NSCAN, 1024>>>();
    k_scan2  <<<1, 128>>>(NSCAN);
    k_scan3  <<<(NN + 255) / 256, 256>>>();
    k_fill   <<<(EE + 255) / 256, 256>>>(ei);
    k_gemm1  <<<(NN + 31) / 32, 256>>>(x, W1);
    k_gather1<<<NN / 8, 256>>>(b1);
    k_bnfinal<<<1, 32>>>();
    k_bnrelu <<<(NN * HIDC + 255) / 256, 256>>>();
    k_gather2<<<NN / 8, 256>>>(W2, b2, out);
}